// round 7
// baseline (speedup 1.0000x reference)
#include <cuda_runtime.h>
#include <math.h>

#define B 16
#define T (1 << 20)
#define NTH 256
#define SUB 256                    // elems per warp sub-chunk
#define NSUB (T / SUB)             // 4096 sub-chunks per row
#define WCH 2048                   // elems per k_wav block (8 warps)
#define NCH (T / WCH)              // 512 k_wav blocks per row
#define CHUNK1 16384               // elems per pass-1 block
#define BPR (T / CHUNK1)           // 64 pass-1 blocks per row
#define STEP (1.0f / 48000.0f)
#define RISE_RATIO 0.66f
#define EPSV 1e-6f
#define PI_F 3.14159265358979f
#define FULL 0xFFFFFFFFu

// scratch (no device-side allocation allowed)
__device__ float  g_partials[B * NSUB];  // per-256-elem sum of f0*STEP
__device__ double g_offsets[B * NSUB];   // ps[b] + exclusive prefix across sub-chunks
__device__ int    g_count[B];            // per-row completion counters (self-resetting)

struct F8 { float v[8]; };

__device__ __forceinline__ F8 ld8_evict_last(const float* p) {
    unsigned r0,r1,r2,r3,r4,r5,r6,r7;
    asm("ld.global.L2::evict_last.v8.b32 {%0,%1,%2,%3,%4,%5,%6,%7}, [%8];"
        : "=r"(r0),"=r"(r1),"=r"(r2),"=r"(r3),"=r"(r4),"=r"(r5),"=r"(r6),"=r"(r7)
        : "l"(p));
    F8 f;
    f.v[0]=__uint_as_float(r0); f.v[1]=__uint_as_float(r1);
    f.v[2]=__uint_as_float(r2); f.v[3]=__uint_as_float(r3);
    f.v[4]=__uint_as_float(r4); f.v[5]=__uint_as_float(r5);
    f.v[6]=__uint_as_float(r6); f.v[7]=__uint_as_float(r7);
    return f;
}
__device__ __forceinline__ F8 ld8_evict_first(const float* p) {
    unsigned r0,r1,r2,r3,r4,r5,r6,r7;
    asm("ld.global.L2::evict_first.v8.b32 {%0,%1,%2,%3,%4,%5,%6,%7}, [%8];"
        : "=r"(r0),"=r"(r1),"=r"(r2),"=r"(r3),"=r"(r4),"=r"(r5),"=r"(r6),"=r"(r7)
        : "l"(p));
    F8 f;
    f.v[0]=__uint_as_float(r0); f.v[1]=__uint_as_float(r1);
    f.v[2]=__uint_as_float(r2); f.v[3]=__uint_as_float(r3);
    f.v[4]=__uint_as_float(r4); f.v[5]=__uint_as_float(r5);
    f.v[6]=__uint_as_float(r6); f.v[7]=__uint_as_float(r7);
    return f;
}

// ------- Pass 1: per-256-elem sums; last block per row scans the row ---------
__global__ __launch_bounds__(NTH) void k_partials(const float* __restrict__ f0,
                                                  const float* __restrict__ ps,
                                                  float* __restrict__ out,
                                                  int out_size) {
    const int b = blockIdx.y, cg = blockIdx.x;
    const int t = threadIdx.x;
    const int lane = t & 31, wid = t >> 5;

    // each warp: 2048 contiguous elems = 8 sub-chunks of 256 (1 v8 load each)
    const float* p = f0 + (size_t)b * T + (size_t)cg * CHUNK1 + (size_t)wid * 2048;
    float ssum[8];
#pragma unroll
    for (int g = 0; g < 2; g++) {               // 2 batches of 4 v8 loads
        F8 x[4];
#pragma unroll
        for (int s = 0; s < 4; s++)
            x[s] = ld8_evict_last(p + (g * 4 + s) * 256 + lane * 8);
#pragma unroll
        for (int s = 0; s < 4; s++) {
            float r = ((x[s].v[0] + x[s].v[1]) + (x[s].v[2] + x[s].v[3]))
                    + ((x[s].v[4] + x[s].v[5]) + (x[s].v[6] + x[s].v[7]));
#pragma unroll
            for (int d = 16; d; d >>= 1) r += __shfl_down_sync(FULL, r, d);
            ssum[g * 4 + s] = r;
        }
    }
    if (lane == 0) {
        const int base = b * NSUB + cg * 64 + wid * 8;
#pragma unroll
        for (int s = 0; s < 8; s++) g_partials[base + s] = ssum[s] * STEP;
    }

    // ---- last block of this row: fp64 scan of 4096 sub-chunk sums ----
    __shared__ int s_last;
    __syncthreads();
    if (t == 0) {
        __threadfence();
        s_last = (atomicAdd(&g_count[b], 1) == BPR - 1);
    }
    __syncthreads();
    if (!s_last) return;
    __threadfence();

    // 256 threads, 16 sub-chunk sums each
    const float4* pr = reinterpret_cast<const float4*>(g_partials + b * NSUB) + t * 4;
    float v[16];
#pragma unroll
    for (int i = 0; i < 4; i++) {
        float4 x = pr[i];
        v[i * 4 + 0] = x.x; v[i * 4 + 1] = x.y; v[i * 4 + 2] = x.z; v[i * 4 + 3] = x.w;
    }
    float pref[16];                               // inclusive fp32 prefix within thread
    float acc = 0.f;
#pragma unroll
    for (int i = 0; i < 16; i++) { acc += v[i]; pref[i] = acc; }
    const double tot = (double)acc;

    double incl = tot;
#pragma unroll
    for (int d = 1; d < 32; d <<= 1) {
        double n = __shfl_up_sync(FULL, incl, d);
        if (lane >= d) incl += n;
    }
    __shared__ double dwsum[NTH / 32];
    __shared__ double dwbase[NTH / 32];
    if (lane == 31) dwsum[wid] = incl;
    __syncthreads();
    if (t == 0) {
        double r = 0.0;
#pragma unroll
        for (int i = 0; i < NTH / 32; i++) { dwbase[i] = r; r += dwsum[i]; }
        g_count[b] = 0;                           // reset for next graph replay
    }
    __syncthreads();

    const double excl = (double)ps[b] + dwbase[wid] + (incl - tot);
    double* po = g_offsets + b * NSUB + t * 16;
    po[0] = excl;
#pragma unroll
    for (int i = 1; i < 16; i++) po[i] = excl + (double)pref[i - 1];

    if (t == NTH - 1) {                           // next_state (unwrapped)
        const long long oi = (long long)B * T + b;
        if (oi < (long long)out_size) out[oi] = (float)(excl + tot);
    }
}

// ------------- Pass 2: per-warp scan + Rosenberg pulse (no barriers) ---------
__global__ __launch_bounds__(NTH) void k_wav(const float* __restrict__ f0,
                                             const float* __restrict__ oq,
                                             float* __restrict__ out) {
    const int b = blockIdx.y, ch = blockIdx.x;
    const int lane = threadIdx.x & 31, wid = threadIdx.x >> 5;
    const int sub = ch * 8 + wid;                 // this warp's 256-elem sub-chunk
    const size_t base = (size_t)b * T + (size_t)sub * SUB;

    // thread owns 8 contiguous elems
    const F8 f = ld8_evict_first(f0 + base + lane * 8);
    const float4* po = reinterpret_cast<const float4*>(oq + base) + lane * 2;
    const float4 qA = __ldcs(&po[0]);
    const float4 qB = __ldcs(&po[1]);

    // thread-local inclusive prefix of 8 (STEP folded in)
    float pr[8];
    float r = f.v[0] * STEP;          pr[0] = r;
#pragma unroll
    for (int i = 1; i < 8; i++) { r = fmaf(f.v[i], STEP, r); pr[i] = r; }
    const float tot = r;

    // single warp scan of thread totals
    float incl = tot;
#pragma unroll
    for (int d = 1; d < 32; d <<= 1) {
        float n = __shfl_up_sync(FULL, incl, d);
        if (lane >= d) incl += n;
    }
    const float excl = incl - tot;

    // absolute phase base (fp64 once per warp's sub-chunk)
    const double based = g_offsets[b * NSUB + sub];
    const float frac = (float)(based - floor(based));     // in [0, 1]
    const float baseph = frac + excl;

    float w[8];
    const float q[8] = { qA.x, qA.y, qA.z, qA.w, qB.x, qB.y, qB.z, qB.w };
#pragma unroll
    for (int j = 0; j < 8; j++) {
        float ph = baseph + pr[j];
        ph -= floorf(ph);                         // wrapped to [0,1)
        const float oqv = q[j];
        const float tp = oqv * RISE_RATIO;
        const float tn = oqv - tp;
        const bool rise = ph < tp;
        const bool open = ph < oqv;
        const float num = rise ? ph : ph - tp;
        const float den = rise ? tp + EPSV : fmaf(2.f, tn, EPSV);
        const float c = __cosf(PI_F * __fdividef(num, den));
        const float res = rise ? fmaf(-0.5f, c, 0.5f) : c;
        w[j] = open ? res : 0.f;
    }

    float4* pw = reinterpret_cast<float4*>(out + base) + lane * 2;
    __stcs(&pw[0], make_float4(w[0], w[1], w[2], w[3]));
    __stcs(&pw[1], make_float4(w[4], w[5], w[6], w[7]));
}

extern "C" void kernel_launch(void* const* d_in, const int* in_sizes, int n_in,
                              void* d_out, int out_size) {
    const float* f0 = (const float*)d_in[0];
    const float* oq = (const float*)d_in[1];
    const float* ps = (const float*)d_in[2];
    float* out = (float*)d_out;

    dim3 grid1(BPR, B);
    k_partials<<<grid1, NTH>>>(f0, ps, out, out_size);
    dim3 grid3(NCH, B);
    k_wav<<<grid3, NTH>>>(f0, oq, out);
}